// round 1
// baseline (speedup 1.0000x reference)
#include <cuda_runtime.h>

#define BATCH   524288
#define IN_A    32
#define IN_S    32
#define DIM     64      // IN_A + IN_S
#define NE      8       // experts
#define NH      64      // expert hidden
#define GHID    32      // gating hidden

#define ROWS_PER_CTA 256
#define THREADS      256

// ---- shared memory layout (float offsets) ----
#define XPITCH   257                      // pad to kill bank conflicts
#define OFF_W1   0
#define SZ_W1    (NE*DIM*NH)              // 32768
#define OFF_X    (OFF_W1 + SZ_W1)         // 32768
#define SZ_X     (DIM*XPITCH)             // 16448
#define OFF_W2   (OFF_X + SZ_X)           // 49216
#define SZ_W2    (NE*NH)                  // 512
#define OFF_B1   (OFF_W2 + SZ_W2)         // 49728
#define SZ_B1    (NE*NH)                  // 512
#define OFF_GW1  (OFF_B1 + SZ_B1)         // 50240
#define SZ_GW1   (IN_S*GHID)              // 1024
#define OFF_GW2  (OFF_GW1 + SZ_GW1)       // 51264
#define SZ_GW2   (GHID*NE)                // 256
#define OFF_GB1  (OFF_GW2 + SZ_GW2)       // 51520
#define SZ_GB1   (GHID)                   // 32
#define OFF_GB2  (OFF_GB1 + SZ_GB1)       // 51552
#define SZ_GB2   (NE)                     // 8
#define OFF_B2   (OFF_GB2 + SZ_GB2)       // 51560
#define SZ_B2    (NE)                     // 8
#define SMEM_FLOATS (OFF_B2 + SZ_B2)      // 51568 -> 206272 bytes

// ---- packed fp32x2 helpers (Blackwell FFMA2 — PTX-only path) ----
__device__ __forceinline__ unsigned long long fma2(unsigned long long a,
                                                   unsigned long long b,
                                                   unsigned long long c) {
    unsigned long long d;
    asm("fma.rn.f32x2 %0, %1, %2, %3;" : "=l"(d) : "l"(a), "l"(b), "l"(c));
    return d;
}
__device__ __forceinline__ unsigned long long pack2(float x, float y) {
    unsigned long long d;
    asm("mov.b64 %0, {%1, %2};" : "=l"(d) : "f"(x), "f"(y));
    return d;
}
__device__ __forceinline__ void unpack2(unsigned long long v, float& x, float& y) {
    asm("mov.b64 {%0, %1}, %2;" : "=f"(x), "=f"(y) : "l"(v));
}

__global__ void __launch_bounds__(THREADS, 1)
moe_kernel(const float* __restrict__ A,   const float* __restrict__ S,
           const float* __restrict__ gw1, const float* __restrict__ gb1,
           const float* __restrict__ gw2, const float* __restrict__ gb2,
           const float* __restrict__ ew1, const float* __restrict__ eb1,
           const float* __restrict__ ew2, const float* __restrict__ eb2,
           float* __restrict__ out)
{
    extern __shared__ float sm[];
    const int tid = threadIdx.x;
    const int R   = blockIdx.x * ROWS_PER_CTA;

    // ---- stage weights (float4-vectorized for the big one) ----
    {
        const float4* src = (const float4*)ew1;
        float4*       dst = (float4*)(sm + OFF_W1);
        #pragma unroll 4
        for (int i = tid; i < SZ_W1 / 4; i += THREADS) dst[i] = src[i];
    }
    for (int i = tid; i < SZ_W2;  i += THREADS) sm[OFF_W2  + i] = ew2[i];
    for (int i = tid; i < SZ_B1;  i += THREADS) sm[OFF_B1  + i] = eb1[i];
    for (int i = tid; i < SZ_GW1; i += THREADS) sm[OFF_GW1 + i] = gw1[i];
    for (int i = tid; i < SZ_GW2; i += THREADS) sm[OFF_GW2 + i] = gw2[i];
    if (tid < GHID) sm[OFF_GB1 + tid] = gb1[tid];
    if (tid < NE)   { sm[OFF_GB2 + tid] = gb2[tid]; sm[OFF_B2 + tid] = eb2[tid]; }

    // ---- stage x tile, transposed: sm_x[col][row], conflict-free via pitch 257 ----
    for (int i = tid; i < ROWS_PER_CTA * IN_A; i += THREADS) {
        int row = i >> 5, col = i & 31;
        sm[OFF_X + col * XPITCH + row] = A[(R + row) * IN_A + col];
    }
    for (int i = tid; i < ROWS_PER_CTA * IN_S; i += THREADS) {
        int row = i >> 5, col = i & 31;
        sm[OFF_X + (IN_A + col) * XPITCH + row] = S[(R + row) * IN_S + col];
    }
    __syncthreads();

    // ================= gating MLP: S -> relu -> logits -> softmax =============
    unsigned long long g2[GHID / 2];
    #pragma unroll
    for (int j = 0; j < GHID / 2; j++)
        g2[j] = *(const unsigned long long*)(sm + OFF_GB1 + 2 * j);

    #pragma unroll 4
    for (int k = 0; k < IN_S; k++) {
        float sv = sm[OFF_X + (IN_A + k) * XPITCH + tid];
        unsigned long long s2 = pack2(sv, sv);
        const unsigned long long* wrow =
            (const unsigned long long*)(sm + OFF_GW1 + k * GHID);
        #pragma unroll
        for (int j = 0; j < GHID / 2; j++) g2[j] = fma2(s2, wrow[j], g2[j]);
    }
    float ghv[GHID];
    #pragma unroll
    for (int j = 0; j < GHID / 2; j++) {
        float a, b; unpack2(g2[j], a, b);
        ghv[2 * j]     = fmaxf(a, 0.f);
        ghv[2 * j + 1] = fmaxf(b, 0.f);
    }

    unsigned long long l2[NE / 2];
    #pragma unroll
    for (int e = 0; e < NE / 2; e++)
        l2[e] = *(const unsigned long long*)(sm + OFF_GB2 + 2 * e);
    #pragma unroll 4
    for (int j = 0; j < GHID; j++) {
        unsigned long long h2 = pack2(ghv[j], ghv[j]);
        const unsigned long long* wrow =
            (const unsigned long long*)(sm + OFF_GW2 + j * NE);
        #pragma unroll
        for (int e = 0; e < NE / 2; e++) l2[e] = fma2(h2, wrow[e], l2[e]);
    }
    float logit[NE];
    #pragma unroll
    for (int e = 0; e < NE / 2; e++) unpack2(l2[e], logit[2 * e], logit[2 * e + 1]);

    float mx = logit[0];
    #pragma unroll
    for (int e = 1; e < NE; e++) mx = fmaxf(mx, logit[e]);
    float prob[NE], se = 0.f;
    #pragma unroll
    for (int e = 0; e < NE; e++) { prob[e] = expf(logit[e] - mx); se += prob[e]; }
    float inv = __fdividef(1.f, se);
    #pragma unroll
    for (int e = 0; e < NE; e++) prob[e] *= inv;

    // ================= experts: x[64] -> relu(h[64]) -> scalar, weighted sum ===
    float result = 0.f;
    #pragma unroll 1
    for (int e = 0; e < NE; e++) {
        unsigned long long acc[NH / 2];
        #pragma unroll
        for (int h = 0; h < NH / 2; h++)
            acc[h] = *(const unsigned long long*)(sm + OFF_B1 + e * NH + 2 * h);

        const float* wbase = sm + OFF_W1 + e * DIM * NH;
        #pragma unroll 2
        for (int k = 0; k < DIM; k++) {
            float xv = sm[OFF_X + k * XPITCH + tid];
            unsigned long long x2 = pack2(xv, xv);
            const ulonglong2* wrow = (const ulonglong2*)(wbase + k * NH);
            #pragma unroll
            for (int q = 0; q < NH / 4; q++) {
                ulonglong2 w = wrow[q];         // LDS.128 broadcast (4 weights)
                acc[2 * q]     = fma2(x2, w.x, acc[2 * q]);
                acc[2 * q + 1] = fma2(x2, w.y, acc[2 * q + 1]);
            }
        }

        // relu + dot with w2 (4 parallel chains to keep latency off the critical path)
        const float* w2r = sm + OFF_W2 + e * NH;
        float p0 = 0.f, p1 = 0.f, p2 = 0.f, p3 = 0.f;
        #pragma unroll
        for (int h = 0; h < NH / 4; h++) {
            float a, b, c, d;
            unpack2(acc[2 * h],     a, b);
            unpack2(acc[2 * h + 1], c, d);
            p0 = fmaf(fmaxf(a, 0.f), w2r[4 * h],     p0);
            p1 = fmaf(fmaxf(b, 0.f), w2r[4 * h + 1], p1);
            p2 = fmaf(fmaxf(c, 0.f), w2r[4 * h + 2], p2);
            p3 = fmaf(fmaxf(d, 0.f), w2r[4 * h + 3], p3);
        }
        float eo = (p0 + p1) + (p2 + p3) + sm[OFF_B2 + e];
        result = fmaf(prob[e], eo, result);
    }

    out[R + tid] = result;
}

extern "C" void kernel_launch(void* const* d_in, const int* in_sizes, int n_in,
                              void* d_out, int out_size)
{
    const float* A   = (const float*)d_in[0];
    const float* S   = (const float*)d_in[1];
    const float* gw1 = (const float*)d_in[2];
    const float* gb1 = (const float*)d_in[3];
    const float* gw2 = (const float*)d_in[4];
    const float* gb2 = (const float*)d_in[5];
    const float* ew1 = (const float*)d_in[6];
    const float* eb1 = (const float*)d_in[7];
    const float* ew2 = (const float*)d_in[8];
    const float* eb2 = (const float*)d_in[9];
    float* out = (float*)d_out;

    cudaFuncSetAttribute(moe_kernel, cudaFuncAttributeMaxDynamicSharedMemorySize,
                         SMEM_FLOATS * (int)sizeof(float));

    moe_kernel<<<BATCH / ROWS_PER_CTA, THREADS, SMEM_FLOATS * sizeof(float)>>>(
        A, S, gw1, gb1, gw2, gb2, ew1, eb1, ew2, eb2, out);
}

// round 3
// speedup vs baseline: 3.9821x; 3.9821x over previous
#include <cuda_runtime.h>
#include <cuda_fp16.h>
#include <cstdint>

#define BATCH   524288
#define DIM     64
#define NE      8
#define NH      64
#define GHID    32

#define TILE_M  128
#define NTILES  (BATCH / TILE_M)   // 4096
#define NCTAS   148
#define THREADS 256
#define NSUB    8                  // 8 x m16 substeps per tile

// ---------------- smem byte layout ----------------
#define OFF_RAW0   0        // raw fp32 x [128][64] (A|S) = 32768
#define OFF_RAW1   32768
#define OFF_XHI    65536    // fp16 [128][64] SW128 = 16384
#define OFF_XLO    81920
#define OFF_ST     98304    // fp32 S transposed [32][129] = 16512
#define OFF_GW1    114816   // fp32 [32][32]
#define OFF_GW2    118912   // fp32 [32][8]
#define OFF_GB1    119936   // fp32 [32]
#define OFF_GB2    120064   // fp32 [8]
#define OFF_PROB   120096   // fp32 [128][8]
#define OFF_EO     124192   // fp32 [128][8]
#define OFF_PLOG   128288   // fp32 [2][128][8]
#define OFF_W2S    136480   // fp32 [8][64]
#define OFF_B1S    138528   // fp32 [8][64]
#define SMEM_BYTES 140576

#define SW(o) ((o) ^ (((o) >> 3) & 0x70))

static __device__ __forceinline__ uint32_t smem_u32(const void* p) {
    uint32_t a;
    asm("{ .reg .u64 t; cvta.to.shared.u64 t, %1; cvt.u32.u64 %0, t; }" : "=r"(a) : "l"(p));
    return a;
}
static __device__ __forceinline__ void cpasync16(uint32_t dst, const void* src) {
    size_t g = __cvta_generic_to_global(src);
    asm volatile("cp.async.cg.shared.global [%0], [%1], 16;" :: "r"(dst), "l"(g));
}
#define CP_COMMIT asm volatile("cp.async.commit_group;" ::: "memory")
#define CP_WAIT0  asm volatile("cp.async.wait_group 0;" ::: "memory")

static __device__ __forceinline__ void ldsm4(uint32_t* r, uint32_t addr) {
    asm volatile("ldmatrix.sync.aligned.m8n8.x4.shared.b16 {%0,%1,%2,%3}, [%4];"
                 : "=r"(r[0]), "=r"(r[1]), "=r"(r[2]), "=r"(r[3]) : "r"(addr));
}
static __device__ __forceinline__ void mma16816(float* c, const uint32_t* a,
                                                uint32_t b0, uint32_t b1) {
    asm volatile(
        "mma.sync.aligned.m16n8k16.row.col.f32.f16.f16.f32 "
        "{%0,%1,%2,%3}, {%4,%5,%6,%7}, {%8,%9}, {%0,%1,%2,%3};"
        : "+f"(c[0]), "+f"(c[1]), "+f"(c[2]), "+f"(c[3])
        : "r"(a[0]), "r"(a[1]), "r"(a[2]), "r"(a[3]), "r"(b0), "r"(b1));
}

// ---- packed fp32x2 helpers ----
typedef unsigned long long ull;
static __device__ __forceinline__ ull fma2(ull a, ull b, ull c) {
    ull d;
    asm("fma.rn.f32x2 %0, %1, %2, %3;" : "=l"(d) : "l"(a), "l"(b), "l"(c));
    return d;
}
static __device__ __forceinline__ ull pack2(float x, float y) {
    ull d;
    asm("mov.b64 %0, {%1, %2};" : "=l"(d) : "f"(x), "f"(y));
    return d;
}
static __device__ __forceinline__ void unpack2(ull v, float& x, float& y) {
    asm("mov.b64 {%0, %1}, %2;" : "=f"(x), "=f"(y) : "l"(v));
}

static __device__ __forceinline__ uint32_t packh2(float a, float b) {
    __half ha = __float2half_rn(a), hb = __float2half_rn(b);
    return ((uint32_t)__half_as_ushort(hb) << 16) | __half_as_ushort(ha);
}

__global__ void __launch_bounds__(THREADS, 1)
moe_mma_kernel(const float* __restrict__ A,   const float* __restrict__ S,
               const float* __restrict__ gw1, const float* __restrict__ gb1,
               const float* __restrict__ gw2, const float* __restrict__ gb2,
               const float* __restrict__ ew1, const float* __restrict__ eb1,
               const float* __restrict__ ew2, const float* __restrict__ eb2,
               float* __restrict__ out)
{
    extern __shared__ char smem[];
    float* smf = (float*)smem;
    const uint32_t sbase = smem_u32(smem);
    const int tid  = threadIdx.x;
    const int lane = tid & 31;
    const int wid  = tid >> 5;          // warp == expert id

    // ---- stage small fp32 weights in smem ----
    for (int i = tid; i < GHID * GHID; i += THREADS) smf[OFF_GW1 / 4 + i] = gw1[i];
    for (int i = tid; i < GHID * NE;   i += THREADS) smf[OFF_GW2 / 4 + i] = gw2[i];
    for (int i = tid; i < NE * NH;     i += THREADS) {
        smf[OFF_W2S / 4 + i] = ew2[i];
        smf[OFF_B1S / 4 + i] = eb1[i];
    }
    if (tid < GHID) smf[OFF_GB1 / 4 + tid] = gb1[tid];
    if (tid < NE)   smf[OFF_GB2 / 4 + tid] = gb2[tid];
    const float b2v = eb2[wid];

    // ---- load this warp's expert W1 into B-fragment registers (hi/lo split) ----
    // B frag n8k16: b0 holds (k=(lane&3)*2+{0,1}, n=lane>>2); b1 same with k+8
    uint32_t bh[8][4][2], bl[8][4][2];
    {
        const float* we = ew1 + wid * DIM * NH;   // [k][n] row-major, n fastest
        const int n  = (lane >> 2);
        const int kb = (lane & 3) * 2;
        #pragma unroll
        for (int nf = 0; nf < 8; nf++) {
            #pragma unroll
            for (int kk = 0; kk < 4; kk++) {
                const int k0 = kk * 16 + kb;
                float w00 = we[(k0 + 0) * NH + nf * 8 + n];
                float w01 = we[(k0 + 1) * NH + nf * 8 + n];
                float w10 = we[(k0 + 8) * NH + nf * 8 + n];
                float w11 = we[(k0 + 9) * NH + nf * 8 + n];
                __half h00 = __float2half_rn(w00), h01 = __float2half_rn(w01);
                __half h10 = __float2half_rn(w10), h11 = __float2half_rn(w11);
                bh[nf][kk][0] = ((uint32_t)__half_as_ushort(h01) << 16) | __half_as_ushort(h00);
                bh[nf][kk][1] = ((uint32_t)__half_as_ushort(h11) << 16) | __half_as_ushort(h10);
                bl[nf][kk][0] = packh2(w00 - __half2float(h00), w01 - __half2float(h01));
                bl[nf][kk][1] = packh2(w10 - __half2float(h10), w11 - __half2float(h11));
            }
        }
    }

    // ---- prefetch first tile ----
    {
        const int rowBase = blockIdx.x * TILE_M;
        #pragma unroll
        for (int w = 0; w < 8; w++) {
            int i = tid + w * THREADS, row = i >> 4, c = i & 15;
            const float* src = (c < 8) ? A + (rowBase + row) * 32 + c * 4
                                       : S + (rowBase + row) * 32 + (c - 8) * 4;
            cpasync16(sbase + OFF_RAW0 + row * 256 + c * 16, src);
        }
        CP_COMMIT;
    }
    __syncthreads();

    // per-lane ldmatrix address components
    const int rl = (lane & 7) + ((lane >> 3) & 1) * 8;     // row within 16
    const uint32_t pb  = (uint32_t)(rl * 128 + ((lane >> 4) * 16));
    const uint32_t swt = ((uint32_t)(rl * 128) >> 3) & 0x70;

    int buf = 0;
    for (int tile = blockIdx.x; tile < NTILES; tile += NCTAS) {
        const int rowBase = tile * TILE_M;
        CP_WAIT0;
        __syncthreads();

        const uint32_t rawoff = buf ? OFF_RAW1 : OFF_RAW0;

        // ---- convert raw fp32 -> fp16 hi/lo (SW128), stash transposed fp32 S ----
        #pragma unroll
        for (int w = 0; w < 8; w++) {
            int i = tid + w * THREADS, row = i >> 4, c4 = i & 15;
            float4 v = *(const float4*)(smem + rawoff + row * 256 + c4 * 16);
            __half h0 = __float2half_rn(v.x), h1 = __float2half_rn(v.y);
            __half h2 = __float2half_rn(v.z), h3 = __float2half_rn(v.w);
            uint2 hp, lp;
            hp.x = ((uint32_t)__half_as_ushort(h1) << 16) | __half_as_ushort(h0);
            hp.y = ((uint32_t)__half_as_ushort(h3) << 16) | __half_as_ushort(h2);
            lp.x = packh2(v.x - __half2float(h0), v.y - __half2float(h1));
            lp.y = packh2(v.z - __half2float(h2), v.w - __half2float(h3));
            uint32_t off = SW((uint32_t)(row * 128 + c4 * 8));
            *(uint2*)(smem + OFF_XHI + off) = hp;
            *(uint2*)(smem + OFF_XLO + off) = lp;
            if (c4 >= 8) {   // S columns -> transposed fp32 for gating
                int k = (c4 - 8) * 4;
                smf[OFF_ST / 4 + (k + 0) * 129 + row] = v.x;
                smf[OFF_ST / 4 + (k + 1) * 129 + row] = v.y;
                smf[OFF_ST / 4 + (k + 2) * 129 + row] = v.z;
                smf[OFF_ST / 4 + (k + 3) * 129 + row] = v.w;
            }
        }
        __syncthreads();

        // ---- prefetch next tile into the other raw buffer ----
        {
            int nt = tile + NCTAS;
            if (nt < NTILES) {
                const int rb = nt * TILE_M;
                const uint32_t doff = buf ? OFF_RAW0 : OFF_RAW1;
                #pragma unroll
                for (int w = 0; w < 8; w++) {
                    int i = tid + w * THREADS, row = i >> 4, c = i & 15;
                    const float* src = (c < 8) ? A + (rb + row) * 32 + c * 4
                                               : S + (rb + row) * 32 + (c - 8) * 4;
                    cpasync16(sbase + doff + row * 256 + c * 16, src);
                }
            }
            CP_COMMIT;
        }

        // ---- gating MLP (fp32), 2 threads per row split the 32 hidden units ----
        {
            const int t = tid & 127, grp = tid >> 7, jb = grp * 16;
            ull g2[8];
            #pragma unroll
            for (int p = 0; p < 8; p++)
                g2[p] = *(const ull*)(smf + OFF_GB1 / 4 + jb + 2 * p);
            #pragma unroll 4
            for (int k = 0; k < GHID; k++) {
                float sv = smf[OFF_ST / 4 + k * 129 + t];
                ull s2 = pack2(sv, sv);
                const ull* wr = (const ull*)(smf + OFF_GW1 / 4 + k * GHID + jb);
                #pragma unroll
                for (int p = 0; p < 8; p++) g2[p] = fma2(s2, wr[p], g2[p]);
            }
            ull l2[4];
            #pragma unroll
            for (int e2 = 0; e2 < 4; e2++)
                l2[e2] = grp ? 0ull : *(const ull*)(smf + OFF_GB2 / 4 + 2 * e2);
            #pragma unroll
            for (int p = 0; p < 8; p++) {
                float a, b; unpack2(g2[p], a, b);
                a = fmaxf(a, 0.f); b = fmaxf(b, 0.f);
                ull pa = pack2(a, a), pb2 = pack2(b, b);
                const ull* wa = (const ull*)(smf + OFF_GW2 / 4 + (jb + 2 * p) * NE);
                const ull* wb = (const ull*)(smf + OFF_GW2 / 4 + (jb + 2 * p + 1) * NE);
                #pragma unroll
                for (int e2 = 0; e2 < 4; e2++) {
                    l2[e2] = fma2(pa, wa[e2], l2[e2]);
                    l2[e2] = fma2(pb2, wb[e2], l2[e2]);
                }
            }
            ull* dst = (ull*)(smf + OFF_PLOG / 4 + (grp * 128 + t) * NE);
            #pragma unroll
            for (int e2 = 0; e2 < 4; e2++) dst[e2] = l2[e2];
        }
        __syncthreads();

        if (tid < 128) {   // combine halves, softmax -> probs
            float logit[NE];
            #pragma unroll
            for (int e = 0; e < NE; e++)
                logit[e] = smf[OFF_PLOG / 4 + tid * NE + e]
                         + smf[OFF_PLOG / 4 + (128 + tid) * NE + e];
            float mx = logit[0];
            #pragma unroll
            for (int e = 1; e < NE; e++) mx = fmaxf(mx, logit[e]);
            float se = 0.f, pr[NE];
            #pragma unroll
            for (int e = 0; e < NE; e++) { pr[e] = expf(logit[e] - mx); se += pr[e]; }
            float inv = __fdividef(1.f, se);
            #pragma unroll
            for (int e = 0; e < NE; e++) smf[OFF_PROB / 4 + tid * NE + e] = pr[e] * inv;
        }

        // ---- expert GEMM: 8 substeps of m16, warp = expert ----
        const float* b1w = smf + OFF_B1S / 4 + wid * NH + (lane & 3) * 2;
        const float* w2w = smf + OFF_W2S / 4 + wid * NH + (lane & 3) * 2;
        #pragma unroll 1
        for (int sub = 0; sub < NSUB; sub++) {
            float c[8][4];
            #pragma unroll
            for (int nf = 0; nf < 8; nf++) {
                float b0 = b1w[nf * 8], b1_ = b1w[nf * 8 + 1];
                c[nf][0] = b0; c[nf][1] = b1_; c[nf][2] = b0; c[nf][3] = b1_;
            }
            #pragma unroll
            for (int kk = 0; kk < 4; kk++) {
                uint32_t ah[4], al[4];
                uint32_t off = (uint32_t)(sub * 2048) + ((pb + kk * 32) ^ swt);
                ldsm4(ah, sbase + OFF_XHI + off);
                ldsm4(al, sbase + OFF_XLO + off);
                #pragma unroll
                for (int nf = 0; nf < 8; nf++) mma16816(c[nf], ah, bh[nf][kk][0], bh[nf][kk][1]);
                #pragma unroll
                for (int nf = 0; nf < 8; nf++) mma16816(c[nf], ah, bl[nf][kk][0], bl[nf][kk][1]);
                #pragma unroll
                for (int nf = 0; nf < 8; nf++) mma16816(c[nf], al, bh[nf][kk][0], bh[nf][kk][1]);
            }
            // relu + dot(w2): per-thread partial over its 16 cols, quad reduce
            float p0 = 0.f, p1 = 0.f;
            #pragma unroll
            for (int nf = 0; nf < 8; nf++) {
                float w0 = w2w[nf * 8], w1 = w2w[nf * 8 + 1];
                p0 = fmaf(fmaxf(c[nf][0], 0.f), w0, p0);
                p0 = fmaf(fmaxf(c[nf][1], 0.f), w1, p0);
                p1 = fmaf(fmaxf(c[nf][2], 0.f), w0, p1);
                p1 = fmaf(fmaxf(c[nf][3], 0.f), w1, p1);
            }
            p0 += __shfl_xor_sync(0xFFFFFFFFu, p0, 1);
            p0 += __shfl_xor_sync(0xFFFFFFFFu, p0, 2);
            p1 += __shfl_xor_sync(0xFFFFFFFFu, p1, 1);
            p1 += __shfl_xor_sync(0xFFFFFFFFu, p1, 2);
            if ((lane & 3) == 0) {
                int r = sub * 16 + (lane >> 2);
                smf[OFF_EO / 4 + r * NE + wid]       = p0 + b2v;
                smf[OFF_EO / 4 + (r + 8) * NE + wid] = p1 + b2v;
            }
        }
        __syncthreads();

        // ---- final: weighted sum over experts ----
        if (tid < 128) {
            float r = 0.f;
            #pragma unroll
            for (int e = 0; e < NE; e++)
                r = fmaf(smf[OFF_PROB / 4 + tid * NE + e],
                         smf[OFF_EO / 4 + tid * NE + e], r);
            out[rowBase + tid] = r;
        }
        buf ^= 1;
    }
}

extern "C" void kernel_launch(void* const* d_in, const int* in_sizes, int n_in,
                              void* d_out, int out_size)
{
    (void)in_sizes; (void)n_in; (void)out_size;
    const float* A   = (const float*)d_in[0];
    const float* S   = (const float*)d_in[1];
    const float* gw1 = (const float*)d_in[2];
    const float* gb1 = (const float*)d_in[3];
    const float* gw2 = (const float*)d_in[4];
    const float* gb2 = (const float*)d_in[5];
    const float* ew1 = (const float*)d_in[6];
    const float* eb1 = (const float*)d_in[7];
    const float* ew2 = (const float*)d_in[8];
    const float* eb2 = (const float*)d_in[9];
    float* out = (float*)d_out;

    cudaFuncSetAttribute(moe_mma_kernel, cudaFuncAttributeMaxDynamicSharedMemorySize, SMEM_BYTES);
    moe_mma_kernel<<<NCTAS, THREADS, SMEM_BYTES>>>(
        A, S, gw1, gb1, gw2, gb2, ew1, eb1, ew2, eb2, out);
}

// round 4
// speedup vs baseline: 5.6016x; 1.4067x over previous
#include <cuda_runtime.h>
#include <cuda_fp16.h>
#include <cstdint>

#define BATCH   524288
#define DIM     64
#define NE      8
#define NH      64
#define GHID    32

#define TILE_M  128
#define NTILES  (BATCH / TILE_M)   // 4096
#define GRID    296                // 2 CTAs per SM
#define THREADS 256
#define NSUB    8

// ---------------- smem byte layout ----------------
#define OFF_RAW    0        // raw fp32 x [128][64] = 32768
#define OFF_XHI    32768    // fp16 [128][64] SW128 = 16384
#define OFF_XLO    49152    // fp16 [128][64] SW128 = 16384
#define OFF_ST     65536    // fp32 S transposed [32][129] = 16512
#define OFF_GW1    82048    // fp32 [32][32] = 4096
#define OFF_GW2    86144    // fp32 [32][8] = 1024
#define OFF_GB1    87168    // fp32 [32]
#define OFF_GB2    87296    // fp32 [8]
#define OFF_PROB   87328    // fp32 [128][8] = 4096
#define OFF_EO     91424    // fp32 [128][8] = 4096
#define OFF_PLOG   95520    // fp32 [2][128][8] = 8192
#define OFF_W2S    103712   // fp32 [8][64] = 2048
#define OFF_B1S    105760   // fp32 [8][64] = 2048
#define SMEM_BYTES 107808

#define SW(o) ((o) ^ (((o) >> 3) & 0x70))

static __device__ __forceinline__ uint32_t smem_u32(const void* p) {
    uint32_t a;
    asm("{ .reg .u64 t; cvta.to.shared.u64 t, %1; cvt.u32.u64 %0, t; }" : "=r"(a) : "l"(p));
    return a;
}
static __device__ __forceinline__ void cpasync16(uint32_t dst, const void* src) {
    size_t g = __cvta_generic_to_global(src);
    asm volatile("cp.async.cg.shared.global [%0], [%1], 16;" :: "r"(dst), "l"(g));
}
#define CP_COMMIT asm volatile("cp.async.commit_group;" ::: "memory")
#define CP_WAIT0  asm volatile("cp.async.wait_group 0;" ::: "memory")

static __device__ __forceinline__ void ldsm4(uint32_t* r, uint32_t addr) {
    asm volatile("ldmatrix.sync.aligned.m8n8.x4.shared.b16 {%0,%1,%2,%3}, [%4];"
                 : "=r"(r[0]), "=r"(r[1]), "=r"(r[2]), "=r"(r[3]) : "r"(addr));
}
static __device__ __forceinline__ void mma16816(float* c, const uint32_t* a,
                                                uint32_t b0, uint32_t b1) {
    asm volatile(
        "mma.sync.aligned.m16n8k16.row.col.f32.f16.f16.f32 "
        "{%0,%1,%2,%3}, {%4,%5,%6,%7}, {%8,%9}, {%0,%1,%2,%3};"
        : "+f"(c[0]), "+f"(c[1]), "+f"(c[2]), "+f"(c[3])
        : "r"(a[0]), "r"(a[1]), "r"(a[2]), "r"(a[3]), "r"(b0), "r"(b1));
}

typedef unsigned long long ull;
static __device__ __forceinline__ ull fma2(ull a, ull b, ull c) {
    ull d;
    asm("fma.rn.f32x2 %0, %1, %2, %3;" : "=l"(d) : "l"(a), "l"(b), "l"(c));
    return d;
}
static __device__ __forceinline__ ull pack2(float x, float y) {
    ull d;
    asm("mov.b64 %0, {%1, %2};" : "=l"(d) : "f"(x), "f"(y));
    return d;
}
static __device__ __forceinline__ void unpack2(ull v, float& x, float& y) {
    asm("mov.b64 {%0, %1}, %2;" : "=f"(x), "=f"(y) : "l"(v));
}
static __device__ __forceinline__ uint32_t packh2(float a, float b) {
    __half ha = __float2half_rn(a), hb = __float2half_rn(b);
    return ((uint32_t)__half_as_ushort(hb) << 16) | __half_as_ushort(ha);
}

__global__ void __launch_bounds__(THREADS, 2)
moe_mma_kernel(const float* __restrict__ A,   const float* __restrict__ S,
               const float* __restrict__ gw1, const float* __restrict__ gb1,
               const float* __restrict__ gw2, const float* __restrict__ gb2,
               const float* __restrict__ ew1, const float* __restrict__ eb1,
               const float* __restrict__ ew2, const float* __restrict__ eb2,
               float* __restrict__ out)
{
    extern __shared__ char smem[];
    float* smf = (float*)smem;
    const uint32_t sbase = smem_u32(smem);
    const int tid  = threadIdx.x;
    const int lane = tid & 31;
    const int wid  = tid >> 5;          // warp == expert id

    // ---- stage small fp32 weights ----
    for (int i = tid; i < GHID * GHID; i += THREADS) smf[OFF_GW1 / 4 + i] = gw1[i];
    for (int i = tid; i < GHID * NE;   i += THREADS) smf[OFF_GW2 / 4 + i] = gw2[i];
    for (int i = tid; i < NE * NH;     i += THREADS) {
        smf[OFF_W2S / 4 + i] = ew2[i];
        smf[OFF_B1S / 4 + i] = eb1[i];
    }
    if (tid < GHID) smf[OFF_GB1 / 4 + tid] = gb1[tid];
    if (tid < NE)   smf[OFF_GB2 / 4 + tid] = gb2[tid];
    const float b2v = eb2[wid];

    // ---- expert W1 B-fragments in registers (single fp16 rounding) ----
    uint32_t bh[8][4][2];
    {
        const float* we = ew1 + wid * DIM * NH;
        const int n  = (lane >> 2);
        const int kb = (lane & 3) * 2;
        #pragma unroll
        for (int nf = 0; nf < 8; nf++) {
            #pragma unroll
            for (int kk = 0; kk < 4; kk++) {
                const int k0 = kk * 16 + kb;
                bh[nf][kk][0] = packh2(we[(k0 + 0) * NH + nf * 8 + n],
                                       we[(k0 + 1) * NH + nf * 8 + n]);
                bh[nf][kk][1] = packh2(we[(k0 + 8) * NH + nf * 8 + n],
                                       we[(k0 + 9) * NH + nf * 8 + n]);
            }
        }
    }

    // ---- prefetch first tile into RAW ----
    {
        const int rowBase = blockIdx.x * TILE_M;
        #pragma unroll
        for (int w = 0; w < 8; w++) {
            int i = tid + w * THREADS, row = i >> 4, c = i & 15;
            const float* src = (c < 8) ? A + (rowBase + row) * 32 + c * 4
                                       : S + (rowBase + row) * 32 + (c - 8) * 4;
            cpasync16(sbase + OFF_RAW + row * 256 + c * 16, src);
        }
        CP_COMMIT;
    }

    const int rl = (lane & 7) + ((lane >> 3) & 1) * 8;
    const uint32_t pb  = (uint32_t)(rl * 128 + ((lane >> 4) * 16));
    const uint32_t swt = ((uint32_t)(rl * 128) >> 3) & 0x70;

    for (int tile = blockIdx.x; tile < NTILES; tile += GRID) {
        const int rowBase = tile * TILE_M;
        CP_WAIT0;
        __syncthreads();

        // ---- convert raw fp32 -> fp16 hi/lo (SW128) + transposed fp32 S ----
        #pragma unroll
        for (int w = 0; w < 8; w++) {
            int i = tid + w * THREADS, row = i >> 4, c4 = i & 15;
            float4 v = *(const float4*)(smem + OFF_RAW + row * 256 + c4 * 16);
            __half h0 = __float2half_rn(v.x), h1 = __float2half_rn(v.y);
            __half h2 = __float2half_rn(v.z), h3 = __float2half_rn(v.w);
            uint2 hp, lp;
            hp.x = ((uint32_t)__half_as_ushort(h1) << 16) | __half_as_ushort(h0);
            hp.y = ((uint32_t)__half_as_ushort(h3) << 16) | __half_as_ushort(h2);
            lp.x = packh2(v.x - __half2float(h0), v.y - __half2float(h1));
            lp.y = packh2(v.z - __half2float(h2), v.w - __half2float(h3));
            uint32_t off = SW((uint32_t)(row * 128 + c4 * 8));
            *(uint2*)(smem + OFF_XHI + off) = hp;
            *(uint2*)(smem + OFF_XLO + off) = lp;
            if (c4 >= 8) {
                int k = (c4 - 8) * 4;
                smf[OFF_ST / 4 + (k + 0) * 129 + row] = v.x;
                smf[OFF_ST / 4 + (k + 1) * 129 + row] = v.y;
                smf[OFF_ST / 4 + (k + 2) * 129 + row] = v.z;
                smf[OFF_ST / 4 + (k + 3) * 129 + row] = v.w;
            }
        }
        __syncthreads();

        // ---- prefetch next tile into RAW (raw consumed above) ----
        {
            int nt = tile + GRID;
            if (nt < NTILES) {
                const int rb = nt * TILE_M;
                #pragma unroll
                for (int w = 0; w < 8; w++) {
                    int i = tid + w * THREADS, row = i >> 4, c = i & 15;
                    const float* src = (c < 8) ? A + (rb + row) * 32 + c * 4
                                               : S + (rb + row) * 32 + (c - 8) * 4;
                    cpasync16(sbase + OFF_RAW + row * 256 + c * 16, src);
                }
            }
            CP_COMMIT;
        }

        // ---- gating MLP (fp32), 2 threads per row ----
        {
            const int t = tid & 127, grp = tid >> 7, jb = grp * 16;
            ull g2[8];
            #pragma unroll
            for (int p = 0; p < 8; p++)
                g2[p] = *(const ull*)(smf + OFF_GB1 / 4 + jb + 2 * p);
            #pragma unroll 4
            for (int k = 0; k < GHID; k++) {
                float sv = smf[OFF_ST / 4 + k * 129 + t];
                ull s2 = pack2(sv, sv);
                const ull* wr = (const ull*)(smf + OFF_GW1 / 4 + k * GHID + jb);
                #pragma unroll
                for (int p = 0; p < 8; p++) g2[p] = fma2(s2, wr[p], g2[p]);
            }
            ull l2[4];
            #pragma unroll
            for (int e2 = 0; e2 < 4; e2++)
                l2[e2] = grp ? 0ull : *(const ull*)(smf + OFF_GB2 / 4 + 2 * e2);
            #pragma unroll
            for (int p = 0; p < 8; p++) {
                float a, b; unpack2(g2[p], a, b);
                a = fmaxf(a, 0.f); b = fmaxf(b, 0.f);
                ull pa = pack2(a, a), pb2 = pack2(b, b);
                const ull* wa = (const ull*)(smf + OFF_GW2 / 4 + (jb + 2 * p) * NE);
                const ull* wb = (const ull*)(smf + OFF_GW2 / 4 + (jb + 2 * p + 1) * NE);
                #pragma unroll
                for (int e2 = 0; e2 < 4; e2++) {
                    l2[e2] = fma2(pa, wa[e2], l2[e2]);
                    l2[e2] = fma2(pb2, wb[e2], l2[e2]);
                }
            }
            ull* dst = (ull*)(smf + OFF_PLOG / 4 + (grp * 128 + t) * NE);
            #pragma unroll
            for (int e2 = 0; e2 < 4; e2++) dst[e2] = l2[e2];
        }
        __syncthreads();

        if (tid < 128) {   // combine halves, softmax -> probs
            float logit[NE];
            #pragma unroll
            for (int e = 0; e < NE; e++)
                logit[e] = smf[OFF_PLOG / 4 + tid * NE + e]
                         + smf[OFF_PLOG / 4 + (128 + tid) * NE + e];
            float mx = logit[0];
            #pragma unroll
            for (int e = 1; e < NE; e++) mx = fmaxf(mx, logit[e]);
            float se = 0.f, pr[NE];
            #pragma unroll
            for (int e = 0; e < NE; e++) { pr[e] = __expf(logit[e] - mx); se += pr[e]; }
            float inv = __fdividef(1.f, se);
            #pragma unroll
            for (int e = 0; e < NE; e++) smf[OFF_PROB / 4 + tid * NE + e] = pr[e] * inv;
        }

        // ---- expert GEMM: 2-product (x hi/lo) x W(fp16) ----
        const float* b1w = smf + OFF_B1S / 4 + wid * NH + (lane & 3) * 2;
        const float* w2w = smf + OFF_W2S / 4 + wid * NH + (lane & 3) * 2;
        #pragma unroll 1
        for (int sub = 0; sub < NSUB; sub++) {
            float c[8][4];
            #pragma unroll
            for (int nf = 0; nf < 8; nf++) {
                float b0 = b1w[nf * 8], b1_ = b1w[nf * 8 + 1];
                c[nf][0] = b0; c[nf][1] = b1_; c[nf][2] = b0; c[nf][3] = b1_;
            }
            #pragma unroll
            for (int kk = 0; kk < 4; kk++) {
                uint32_t ah[4], al[4];
                uint32_t off = (uint32_t)(sub * 2048) + ((pb + kk * 32) ^ swt);
                ldsm4(ah, sbase + OFF_XHI + off);
                ldsm4(al, sbase + OFF_XLO + off);
                #pragma unroll
                for (int nf = 0; nf < 8; nf++) mma16816(c[nf], ah, bh[nf][kk][0], bh[nf][kk][1]);
                #pragma unroll
                for (int nf = 0; nf < 8; nf++) mma16816(c[nf], al, bh[nf][kk][0], bh[nf][kk][1]);
            }
            float p0 = 0.f, p1 = 0.f;
            #pragma unroll
            for (int nf = 0; nf < 8; nf++) {
                float w0 = w2w[nf * 8], w1 = w2w[nf * 8 + 1];
                p0 = fmaf(fmaxf(c[nf][0], 0.f), w0, p0);
                p0 = fmaf(fmaxf(c[nf][1], 0.f), w1, p0);
                p1 = fmaf(fmaxf(c[nf][2], 0.f), w0, p1);
                p1 = fmaf(fmaxf(c[nf][3], 0.f), w1, p1);
            }
            p0 += __shfl_xor_sync(0xFFFFFFFFu, p0, 1);
            p0 += __shfl_xor_sync(0xFFFFFFFFu, p0, 2);
            p1 += __shfl_xor_sync(0xFFFFFFFFu, p1, 1);
            p1 += __shfl_xor_sync(0xFFFFFFFFu, p1, 2);
            if ((lane & 3) == 0) {
                int r = sub * 16 + (lane >> 2);
                smf[OFF_EO / 4 + r * NE + wid]       = p0 + b2v;
                smf[OFF_EO / 4 + (r + 8) * NE + wid] = p1 + b2v;
            }
        }
        __syncthreads();

        if (tid < 128) {
            float r = 0.f;
            #pragma unroll
            for (int e = 0; e < NE; e++)
                r = fmaf(smf[OFF_PROB / 4 + tid * NE + e],
                         smf[OFF_EO / 4 + tid * NE + e], r);
            out[rowBase + tid] = r;
        }
    }
}

extern "C" void kernel_launch(void* const* d_in, const int* in_sizes, int n_in,
                              void* d_out, int out_size)
{
    (void)in_sizes; (void)n_in; (void)out_size;
    const float* A   = (const float*)d_in[0];
    const float* S   = (const float*)d_in[1];
    const float* gw1 = (const float*)d_in[2];
    const float* gb1 = (const float*)d_in[3];
    const float* gw2 = (const float*)d_in[4];
    const float* gb2 = (const float*)d_in[5];
    const float* ew1 = (const float*)d_in[6];
    const float* eb1 = (const float*)d_in[7];
    const float* ew2 = (const float*)d_in[8];
    const float* eb2 = (const float*)d_in[9];
    float* out = (float*)d_out;

    cudaFuncSetAttribute(moe_mma_kernel, cudaFuncAttributeMaxDynamicSharedMemorySize, SMEM_BYTES);
    moe_mma_kernel<<<GRID, THREADS, SMEM_BYTES>>>(
        A, S, gw1, gb1, gw2, gb2, ew1, eb1, ew2, eb2, out);
}